// round 4
// baseline (speedup 1.0000x reference)
#include <cuda_runtime.h>
#include <cuda_bf16.h>
#include <math.h>
#include <stdint.h>

#define ROWS   32768
#define DDIM   1024
#define MDIM   512
#define BATCH  4
#define SEQ    8192
#define CHUNK  128
#define NCHUNK 64

typedef __nv_bfloat16 bf16;

// ---------------- scratch (static device globals; no allocations) -----------
__device__ __align__(128) bf16  g_xb[ROWS * DDIM];
__device__ __align__(128) bf16  g_hb[ROWS * MDIM];
__device__ __align__(128) bf16  g_qh[ROWS * MDIM];
__device__ __align__(128) bf16  g_kh[ROWS * MDIM];
__device__ __align__(128) bf16  g_vb[ROWS * MDIM];
__device__ __align__(128) bf16  g_pb[ROWS * MDIM];
__device__ __align__(128) bf16  g_ub[ROWS * MDIM];
__device__ __align__(128) bf16  g_lc[ROWS * MDIM];
__device__ __align__(128) bf16  g_rb[ROWS * MDIM];
__device__ __align__(128) float g_carry[BATCH * NCHUNK * MDIM];
__device__ __align__(128) float g_pref [BATCH * NCHUNK * MDIM];
// bf16 weights, [K, N] row-major (direct B operand)
__device__ __align__(128) bf16  g_Wdb [DDIM * MDIM];
__device__ __align__(128) bf16  g_Wqkv[MDIM * 3 * MDIM];   // [512, 1536] q|k|v
__device__ __align__(128) bf16  g_W1b [MDIM * MDIM];
__device__ __align__(128) bf16  g_W2b [MDIM * MDIM];
__device__ __align__(128) bf16  g_Wub [MDIM * DDIM];

__device__ __forceinline__ float gelu_tanh(float x) {
    float x3 = x * x * x;
    float t  = tanhf(0.7978845608028654f * (x + 0.044715f * x3));
    return 0.5f * x * (1.0f + t);
}

// ---------------- PTX helpers ------------------------------------------------
__device__ __forceinline__ unsigned smem_u32(const void* p) {
    unsigned a;
    asm("{ .reg .u64 t; cvta.to.shared.u64 t, %1; cvt.u32.u64 %0, t; }" : "=r"(a) : "l"(p));
    return a;
}
__device__ __forceinline__ void cp16(unsigned s, const void* g) {
    asm volatile("cp.async.cg.shared.global [%0], [%1], 16;\n" :: "r"(s), "l"(g));
}
__device__ __forceinline__ void cp_commit() { asm volatile("cp.async.commit_group;\n"); }
template<int N> __device__ __forceinline__ void cp_wait() {
    asm volatile("cp.async.wait_group %0;\n" :: "n"(N));
}

// ---------------- bf16 mma.sync GEMM, 3-stage pipeline -----------------------
// A [Mrows,K] bf16 row-major, B [K,N] bf16 row-major.
// MODE 0: Cb0 = A@B + bias0                 (bf16)
// MODE 1: Cb0 = gelu(A@B)                   (bf16)
// MODE 2: Cb0 = (*scal) * (extraB - A@B)    (bf16)
// MODE 3: Cf  = A@B + bias0 + extraF        (fp32)
// MODE 4: fused qkv: N=1536, thirds -> (Cb0,bias0) (Cb1,bias1) (Cb2,bias2), out width 512
#define PA 40
#define PB 136
#define ST_A (128 * PA * 2)          // bytes per A stage
#define ST_B (32 * PB * 2)           // bytes per B stage
#define SMEM_TOT (3 * ST_A + 3 * ST_B)

template <int MODE>
__global__ __launch_bounds__(256, 2) void mma_gemm(
    const bf16* __restrict__ A, const bf16* __restrict__ B,
    const float* __restrict__ bias0, const float* __restrict__ bias1,
    const float* __restrict__ bias2,
    const float* __restrict__ extraF, const bf16* __restrict__ extraB,
    const float* __restrict__ scal,
    float* __restrict__ Cf, bf16* __restrict__ Cb0,
    bf16* __restrict__ Cb1, bf16* __restrict__ Cb2,
    int K, int N)
{
    extern __shared__ char smem[];
    const unsigned sbase = smem_u32(smem);

    const int t    = threadIdx.x;
    const int lane = t & 31;
    const int w    = t >> 5;
    const int wm   = w & 1;
    const int wn   = w >> 1;
    const int blockRow = blockIdx.y * 128;
    const int blockCol = blockIdx.x * 128;

    auto sA = [&](int st) { return sbase + (unsigned)st * ST_A; };
    auto sB = [&](int st) { return sbase + 3u * ST_A + (unsigned)st * ST_B; };

    float acc[4][4][4];
#pragma unroll
    for (int mi = 0; mi < 4; mi++)
#pragma unroll
        for (int ni = 0; ni < 4; ni++)
#pragma unroll
            for (int r = 0; r < 4; r++) acc[mi][ni][r] = 0.0f;

    const int KT = K >> 5;   // BK = 32

    auto load_stage = [&](int st, int k0) {
#pragma unroll
        for (int i = 0; i < 2; i++) {
            int c   = t * 2 + i;
            int row = c >> 2;
            int kg  = c & 3;
            cp16(sA(st) + (unsigned)((row * PA + kg * 8) * 2),
                 A + (size_t)(blockRow + row) * K + k0 + kg * 8);
        }
#pragma unroll
        for (int i = 0; i < 2; i++) {
            int c   = t * 2 + i;
            int row = c >> 4;
            int ng  = c & 15;
            cp16(sB(st) + (unsigned)((row * PB + ng * 8) * 2),
                 B + (size_t)(k0 + row) * N + blockCol + ng * 8);
        }
        cp_commit();
    };

    load_stage(0, 0);
    load_stage(1, 32);

    const int l15 = lane & 15;
    const int l16 = lane >> 4;

    for (int kt = 0; kt < KT; kt++) {
        const int cur = kt % 3;
        if (kt + 1 < KT) cp_wait<1>(); else cp_wait<0>();
        __syncthreads();
        if (kt + 2 < KT) load_stage((kt + 2) % 3, (kt + 2) * 32);

#pragma unroll
        for (int ks = 0; ks < 2; ks++) {
            unsigned afr[4][4];
#pragma unroll
            for (int mi = 0; mi < 4; mi++) {
                unsigned addr = sA(cur) +
                    (unsigned)(((wm * 64 + mi * 16 + l15) * PA + ks * 16 + l16 * 8) * 2);
                asm volatile("ldmatrix.sync.aligned.m8n8.x4.shared.b16 {%0,%1,%2,%3}, [%4];\n"
                    : "=r"(afr[mi][0]), "=r"(afr[mi][1]), "=r"(afr[mi][2]), "=r"(afr[mi][3])
                    : "r"(addr));
            }
            unsigned bfr[2][4];
#pragma unroll
            for (int n2 = 0; n2 < 2; n2++) {
                unsigned addr = sB(cur) +
                    (unsigned)(((ks * 16 + l15) * PB + wn * 32 + n2 * 16 + l16 * 8) * 2);
                asm volatile("ldmatrix.sync.aligned.m8n8.x4.trans.shared.b16 {%0,%1,%2,%3}, [%4];\n"
                    : "=r"(bfr[n2][0]), "=r"(bfr[n2][1]), "=r"(bfr[n2][2]), "=r"(bfr[n2][3])
                    : "r"(addr));
            }
#pragma unroll
            for (int mi = 0; mi < 4; mi++)
#pragma unroll
                for (int ni = 0; ni < 4; ni++) {
                    unsigned b0 = bfr[ni >> 1][(ni & 1) * 2 + 0];
                    unsigned b1 = bfr[ni >> 1][(ni & 1) * 2 + 1];
                    asm volatile(
                        "mma.sync.aligned.m16n8k16.row.col.f32.bf16.bf16.f32 "
                        "{%0,%1,%2,%3}, {%4,%5,%6,%7}, {%8,%9}, {%0,%1,%2,%3};\n"
                        : "+f"(acc[mi][ni][0]), "+f"(acc[mi][ni][1]),
                          "+f"(acc[mi][ni][2]), "+f"(acc[mi][ni][3])
                        : "r"(afr[mi][0]), "r"(afr[mi][1]), "r"(afr[mi][2]), "r"(afr[mi][3]),
                          "r"(b0), "r"(b1));
                }
        }
        __syncthreads();   // protect stage reuse distance (cheap vs correctness risk)
    }

    // ---- epilogue ----
    const int grp = lane >> 2;
    const int t4  = lane & 3;
    const float lr = (MODE == 2) ? *scal : 0.0f;

    const float* biasS = bias0;
    bf16* CbS = Cb0;
    int colLocBase;
    int Nout;
    if (MODE == 4) {
        int third = blockIdx.x >> 2;
        biasS = (third == 0) ? bias0 : (third == 1) ? bias1 : bias2;
        CbS   = (third == 0) ? Cb0   : (third == 1) ? Cb1   : Cb2;
        colLocBase = (blockIdx.x & 3) * 128 + wn * 32;
        Nout = MDIM;
    } else {
        colLocBase = blockCol + wn * 32;
        Nout = N;
    }

#pragma unroll
    for (int mi = 0; mi < 4; mi++) {
#pragma unroll
        for (int ni = 0; ni < 4; ni++) {
            int c = colLocBase + ni * 8 + 2 * t4;
            float b0 = 0.f, b1 = 0.f;
            if (MODE == 0 || MODE == 3 || MODE == 4) { b0 = biasS[c]; b1 = biasS[c + 1]; }
#pragma unroll
            for (int h2 = 0; h2 < 2; h2++) {
                size_t r   = (size_t)(blockRow + wm * 64 + mi * 16 + grp + h2 * 8);
                size_t off = r * Nout + c;
                float v0 = acc[mi][ni][h2 * 2 + 0];
                float v1 = acc[mi][ni][h2 * 2 + 1];
                float o0, o1;
                if (MODE == 1)      { o0 = gelu_tanh(v0); o1 = gelu_tanh(v1); }
                else if (MODE == 2) {
                    __nv_bfloat162 e = *reinterpret_cast<const __nv_bfloat162*>(extraB + off);
                    o0 = lr * (__bfloat162float(e.x) - v0);
                    o1 = lr * (__bfloat162float(e.y) - v1);
                }
                else if (MODE == 3) { o0 = v0 + b0 + extraF[off]; o1 = v1 + b1 + extraF[off + 1]; }
                else                { o0 = v0 + b0; o1 = v1 + b1; }
                if (MODE == 3) {
                    *reinterpret_cast<float2*>(Cf + off) = make_float2(o0, o1);
                } else {
                    __nv_bfloat162 p = __floats2bfloat162_rn(o0, o1);
                    *reinterpret_cast<unsigned*>(CbS + off) = *reinterpret_cast<unsigned*>(&p);
                }
            }
        }
    }
}

// ---------------- conversions ------------------------------------------------
__global__ __launch_bounds__(256) void cvt_kernel(const float* __restrict__ s,
                                                  bf16* __restrict__ d, int n4)
{
    int i = blockIdx.x * 256 + threadIdx.x;
    if (i >= n4) return;
    float4 v = reinterpret_cast<const float4*>(s)[i];
    __nv_bfloat162 a = __floats2bfloat162_rn(v.x, v.y);
    __nv_bfloat162 b = __floats2bfloat162_rn(v.z, v.w);
    uint2 ou;
    ou.x = *reinterpret_cast<unsigned*>(&a);
    ou.y = *reinterpret_cast<unsigned*>(&b);
    reinterpret_cast<uint2*>(d)[i] = ou;
}

// W [512,512] fp32 -> g_Wqkv[k*1536 + off + n] bf16
__global__ __launch_bounds__(256) void cvt_qkv(const float* __restrict__ W,
                                               bf16* __restrict__ dst, int off)
{
    int i = blockIdx.x * 256 + threadIdx.x;      // over 512*512/4
    if (i >= MDIM * MDIM / 4) return;
    float4 v = reinterpret_cast<const float4*>(W)[i];
    int k  = i >> 7;
    int n4 = i & 127;
    __nv_bfloat162 a = __floats2bfloat162_rn(v.x, v.y);
    __nv_bfloat162 b = __floats2bfloat162_rn(v.z, v.w);
    uint2 ou;
    ou.x = *reinterpret_cast<unsigned*>(&a);
    ou.y = *reinterpret_cast<unsigned*>(&b);
    *reinterpret_cast<uint2*>(dst + (size_t)k * 1536 + off + n4 * 4) = ou;
}

// ---------------- LayerNorm in place on bf16, warp per row -------------------
__global__ __launch_bounds__(256) void ln_kernel(bf16* __restrict__ Z,
                                                 const float* __restrict__ g,
                                                 const float* __restrict__ b)
{
    int warp = threadIdx.x >> 5;
    int lane = threadIdx.x & 31;
    size_t row = (size_t)blockIdx.x * 8 + warp;
    bf16* zr = Z + row * MDIM;

    float v[16];
    float s = 0.0f, s2 = 0.0f;
#pragma unroll
    for (int j = 0; j < 2; j++) {
        uint4 u = *reinterpret_cast<const uint4*>(zr + (lane + 32 * j) * 8);
        const unsigned* uu = reinterpret_cast<const unsigned*>(&u);
#pragma unroll
        for (int q2 = 0; q2 < 4; q2++) {
            __nv_bfloat162 p = *reinterpret_cast<const __nv_bfloat162*>(&uu[q2]);
            float a0 = __bfloat162float(p.x), a1 = __bfloat162float(p.y);
            v[j * 8 + q2 * 2 + 0] = a0;
            v[j * 8 + q2 * 2 + 1] = a1;
            s += a0 + a1;
            s2 += a0 * a0 + a1 * a1;
        }
    }
#pragma unroll
    for (int o = 16; o; o >>= 1) {
        s  += __shfl_xor_sync(0xffffffffu, s,  o);
        s2 += __shfl_xor_sync(0xffffffffu, s2, o);
    }
    float mu   = s  * (1.0f / MDIM);
    float var  = s2 * (1.0f / MDIM) - mu * mu;
    float rstd = rsqrtf(var + 1e-5f);
#pragma unroll
    for (int j = 0; j < 2; j++) {
        int cbase = (lane + 32 * j) * 8;
        uint4 pk;
        unsigned* pu = reinterpret_cast<unsigned*>(&pk);
#pragma unroll
        for (int q2 = 0; q2 < 4; q2++) {
            float g0 = g[cbase + q2 * 2], g1 = g[cbase + q2 * 2 + 1];
            float b0 = b[cbase + q2 * 2], b1 = b[cbase + q2 * 2 + 1];
            float o0 = (v[j * 8 + q2 * 2 + 0] - mu) * rstd * g0 + b0;
            float o1 = (v[j * 8 + q2 * 2 + 1] - mu) * rstd * g1 + b1;
            __nv_bfloat162 p = __floats2bfloat162_rn(o0, o1);
            pu[q2] = *reinterpret_cast<unsigned*>(&p);
        }
        *reinterpret_cast<uint4*>(zr + cbase) = pk;
    }
}

// ---------------- 3-phase gated scan -----------------------------------------
__global__ __launch_bounds__(512) void scan1(
    const bf16* __restrict__ u, bf16* __restrict__ loc,
    float* __restrict__ carry, const float* __restrict__ ffp)
{
    int m = threadIdx.x, c = blockIdx.x, b = blockIdx.y;
    float g = 1.0f / (1.0f + expf(-*ffp));
    size_t base = ((size_t)b * SEQ + (size_t)c * CHUNK) * MDIM + m;
    float acc = 0.0f;
    for (int s = 0; s < CHUNK; s++) {
        size_t idx = base + (size_t)s * MDIM;
        acc = fmaf(g, acc, __bfloat162float(u[idx]));
        loc[idx] = __float2bfloat16(acc);
    }
    carry[((size_t)b * NCHUNK + c) * MDIM + m] = acc;
}

__global__ __launch_bounds__(512) void scan2(
    const float* __restrict__ carry, float* __restrict__ pref,
    const float* __restrict__ ffp)
{
    int m = threadIdx.x, b = blockIdx.x;
    float g  = 1.0f / (1.0f + expf(-*ffp));
    float gL = powf(g, (float)CHUNK);
    float P = 0.0f;
    for (int c = 0; c < NCHUNK; c++) {
        size_t idx = ((size_t)b * NCHUNK + c) * MDIM + m;
        pref[idx] = P;
        P = fmaf(gL, P, carry[idx]);
    }
}

__global__ __launch_bounds__(512) void scan3(
    const bf16* __restrict__ loc, const float* __restrict__ pref,
    const bf16* __restrict__ q, bf16* __restrict__ ret,
    const float* __restrict__ ffp)
{
    int m = threadIdx.x, c = blockIdx.x, b = blockIdx.y;
    float g = 1.0f / (1.0f + expf(-*ffp));
    float P = pref[((size_t)b * NCHUNK + c) * MDIM + m];
    size_t base = ((size_t)b * SEQ + (size_t)c * CHUNK) * MDIM + m;
    float wgt = g;
    for (int s = 0; s < CHUNK; s++) {
        size_t idx = base + (size_t)s * MDIM;
        float mem = fmaf(wgt, P, __bfloat162float(loc[idx]));
        ret[idx] = __float2bfloat16(__bfloat162float(q[idx]) * mem);
        wgt *= g;
    }
}

// ---------------- launch ------------------------------------------------------
extern "C" void kernel_launch(void* const* d_in, const int* in_sizes, int n_in,
                              void* d_out, int out_size)
{
    const float* x    = (const float*)d_in[0];
    const float* Wd   = (const float*)d_in[1];
    const float* bd   = (const float*)d_in[2];
    const float* Wq   = (const float*)d_in[3];
    const float* bq   = (const float*)d_in[4];
    const float* Wk   = (const float*)d_in[5];
    const float* bk   = (const float*)d_in[6];
    const float* Wv   = (const float*)d_in[7];
    const float* bv   = (const float*)d_in[8];
    const float* gq   = (const float*)d_in[9];
    const float* bqln = (const float*)d_in[10];
    const float* gk   = (const float*)d_in[11];
    const float* bkln = (const float*)d_in[12];
    const float* W1   = (const float*)d_in[13];
    const float* W2   = (const float*)d_in[14];
    const float* Wu   = (const float*)d_in[15];
    const float* bu   = (const float*)d_in[16];
    const float* lr   = (const float*)d_in[17];
    const float* ff   = (const float*)d_in[18];
    float* out = (float*)d_out;

    bf16 *xb, *hb, *qh, *kh, *vb, *pb, *ub, *lc, *rb;
    bf16 *Wdb, *Wqkv, *W1b, *W2b, *Wub;
    float *carry, *pref;
    cudaGetSymbolAddress((void**)&xb, g_xb);
    cudaGetSymbolAddress((void**)&hb, g_hb);
    cudaGetSymbolAddress((void**)&qh, g_qh);
    cudaGetSymbolAddress((void**)&kh, g_kh);
    cudaGetSymbolAddress((void**)&vb, g_vb);
    cudaGetSymbolAddress((void**)&pb, g_pb);
    cudaGetSymbolAddress((void**)&ub, g_ub);
    cudaGetSymbolAddress((void**)&lc, g_lc);
    cudaGetSymbolAddress((void**)&rb, g_rb);
    cudaGetSymbolAddress((void**)&carry, g_carry);
    cudaGetSymbolAddress((void**)&pref,  g_pref);
    cudaGetSymbolAddress((void**)&Wdb,  g_Wdb);
    cudaGetSymbolAddress((void**)&Wqkv, g_Wqkv);
    cudaGetSymbolAddress((void**)&W1b,  g_W1b);
    cudaGetSymbolAddress((void**)&W2b,  g_W2b);
    cudaGetSymbolAddress((void**)&Wub,  g_Wub);

    cudaFuncSetAttribute(mma_gemm<0>, cudaFuncAttributeMaxDynamicSharedMemorySize, SMEM_TOT);
    cudaFuncSetAttribute(mma_gemm<1>, cudaFuncAttributeMaxDynamicSharedMemorySize, SMEM_TOT);
    cudaFuncSetAttribute(mma_gemm<2>, cudaFuncAttributeMaxDynamicSharedMemorySize, SMEM_TOT);
    cudaFuncSetAttribute(mma_gemm<3>, cudaFuncAttributeMaxDynamicSharedMemorySize, SMEM_TOT);
    cudaFuncSetAttribute(mma_gemm<4>, cudaFuncAttributeMaxDynamicSharedMemorySize, SMEM_TOT);

    dim3 tb(256);
    dim3 gM(MDIM / 128, ROWS / 128);     // (4, 256)
    dim3 gQKV(3 * MDIM / 128, ROWS / 128); // (12, 256)
    dim3 gD(DDIM / 128, ROWS / 128);     // (8, 256)

    // launches 1-5 (so ncu -s 5 captures the h-GEMM)
    cvt_kernel<<<ROWS * DDIM / 4 / 256, 256>>>(x, xb, ROWS * DDIM / 4);
    cvt_kernel<<<DDIM * MDIM / 4 / 256, 256>>>(Wd, Wdb, DDIM * MDIM / 4);
    cvt_qkv<<<MDIM * MDIM / 4 / 256, 256>>>(Wq, Wqkv, 0);
    cvt_qkv<<<MDIM * MDIM / 4 / 256, 256>>>(Wk, Wqkv, 512);
    cvt_qkv<<<MDIM * MDIM / 4 / 256, 256>>>(Wv, Wqkv, 1024);

    // 6: h = x@Wd + bd   (ncu capture target)
    mma_gemm<0><<<gM, tb, SMEM_TOT>>>(xb, Wdb, bd, nullptr, nullptr, nullptr, nullptr,
                                      nullptr, nullptr, hb, nullptr, nullptr, DDIM, MDIM);
    // 7: fused qkv
    mma_gemm<4><<<gQKV, tb, SMEM_TOT>>>(hb, Wqkv, bq, bk, bv, nullptr, nullptr,
                                        nullptr, nullptr, qh, kh, vb, MDIM, 3 * MDIM);
    // remaining weight converts
    cvt_kernel<<<MDIM * MDIM / 4 / 256, 256>>>(W1, W1b, MDIM * MDIM / 4);
    cvt_kernel<<<MDIM * MDIM / 4 / 256, 256>>>(W2, W2b, MDIM * MDIM / 4);
    cvt_kernel<<<MDIM * DDIM / 4 / 256, 256>>>(Wu, Wub, MDIM * DDIM / 4);
    // LayerNorms
    ln_kernel<<<ROWS / 8, 256>>>(qh, gq, bqln);
    ln_kernel<<<ROWS / 8, 256>>>(kh, gk, bkln);
    // P = gelu(k@W1)
    mma_gemm<1><<<gM, tb, SMEM_TOT>>>(kh, W1b, nullptr, nullptr, nullptr, nullptr, nullptr,
                                      nullptr, nullptr, pb, nullptr, nullptr, MDIM, MDIM);
    // u = lr*(v - P@W2)
    mma_gemm<2><<<gM, tb, SMEM_TOT>>>(pb, W2b, nullptr, nullptr, nullptr, nullptr, vb,
                                      lr, nullptr, ub, nullptr, nullptr, MDIM, MDIM);
    // scan
    scan1<<<dim3(NCHUNK, BATCH), MDIM>>>(ub, lc, carry, ff);
    scan2<<<BATCH, MDIM>>>(carry, pref, ff);
    scan3<<<dim3(NCHUNK, BATCH), MDIM>>>(lc, pref, qh, rb, ff);
    // out = x + ret@Wu + bu
    mma_gemm<3><<<gD, tb, SMEM_TOT>>>(rb, Wub, bu, nullptr, nullptr, x, nullptr,
                                      nullptr, out, nullptr, nullptr, nullptr, MDIM, DDIM);
}

// round 5
// speedup vs baseline: 1.0147x; 1.0147x over previous
#include <cuda_runtime.h>
#include <cuda_bf16.h>
#include <math.h>
#include <stdint.h>

#define ROWS   32768
#define DDIM   1024
#define MDIM   512
#define BATCH  4
#define SEQ    8192
#define CHUNK  128
#define NCHUNK 64

typedef __nv_bfloat16 bf16;

// ---------------- scratch (static device globals; no allocations) -----------
__device__ __align__(128) bf16  g_xb[ROWS * DDIM];
__device__ __align__(128) bf16  g_hb[ROWS * MDIM];
__device__ __align__(128) bf16  g_qh[ROWS * MDIM];
__device__ __align__(128) bf16  g_kh[ROWS * MDIM];
__device__ __align__(128) bf16  g_vb[ROWS * MDIM];
__device__ __align__(128) bf16  g_pb[ROWS * MDIM];
__device__ __align__(128) bf16  g_ub[ROWS * MDIM];
__device__ __align__(128) bf16  g_lc[ROWS * MDIM];
__device__ __align__(128) bf16  g_rb[ROWS * MDIM];
__device__ __align__(128) float g_carry[BATCH * NCHUNK * MDIM];
__device__ __align__(128) float g_pref [BATCH * NCHUNK * MDIM];
// bf16 weights, [K, N] row-major (direct B operand)
__device__ __align__(128) bf16  g_Wdb [DDIM * MDIM];
__device__ __align__(128) bf16  g_Wqkv[MDIM * 3 * MDIM];   // [512, 1536] q|k|v
__device__ __align__(128) bf16  g_W1b [MDIM * MDIM];
__device__ __align__(128) bf16  g_W2b [MDIM * MDIM];
__device__ __align__(128) bf16  g_Wub [MDIM * DDIM];

__device__ __forceinline__ float gelu_tanh(float x) {
    float x3 = x * x * x;
    float t  = tanhf(0.7978845608028654f * (x + 0.044715f * x3));
    return 0.5f * x * (1.0f + t);
}

// ---------------- PTX helpers ------------------------------------------------
__device__ __forceinline__ void cp16(unsigned s, const void* g) {
    asm volatile("cp.async.cg.shared.global [%0], [%1], 16;\n" :: "r"(s), "l"(g));
}
__device__ __forceinline__ void cp_commit() { asm volatile("cp.async.commit_group;\n"); }
template<int N> __device__ __forceinline__ void cp_wait() {
    asm volatile("cp.async.wait_group %0;\n" :: "n"(N));
}

// ---------------- bf16 mma.sync GEMM, 3-stage, single barrier/iter -----------
// MODE 0: Cb0 = A@B + bias0                 (bf16)
// MODE 1: Cb0 = gelu(A@B)                   (bf16)
// MODE 2: Cb0 = (*scal) * (extraB - A@B)    (bf16)
// MODE 3: Cf  = A@B + bias0 + extraF        (fp32)
// MODE 4: fused qkv: N=1536, thirds -> (Cb0,bias0) (Cb1,bias1) (Cb2,bias2)
#define PA 40
#define PB 136
#define ST_A (128 * PA * 2)
#define ST_B (32 * PB * 2)
#define SMEM_TOT (3 * ST_A + 3 * ST_B)

template <int MODE>
__global__ __launch_bounds__(256, 2) void mma_gemm(
    const bf16* __restrict__ A, const bf16* __restrict__ B,
    const float* __restrict__ bias0, const float* __restrict__ bias1,
    const float* __restrict__ bias2,
    const float* __restrict__ extraF, const bf16* __restrict__ extraB,
    const float* __restrict__ scal,
    float* __restrict__ Cf, bf16* __restrict__ Cb0,
    bf16* __restrict__ Cb1, bf16* __restrict__ Cb2,
    int K, int N)
{
    extern __shared__ char smem[];
    unsigned sbase;
    asm("{ .reg .u64 t; cvta.to.shared.u64 t, %1; cvt.u32.u64 %0, t; }"
        : "=r"(sbase) : "l"(smem));

    const int t    = threadIdx.x;
    const int lane = t & 31;
    const int w    = t >> 5;
    const int wm   = w & 1;
    const int wn   = w >> 1;
    const int blockRow = blockIdx.y * 128;
    const int blockCol = blockIdx.x * 128;

    auto sA = [&](int st) { return sbase + (unsigned)st * ST_A; };
    auto sB = [&](int st) { return sbase + 3u * ST_A + (unsigned)st * ST_B; };

    float acc[4][4][4];
#pragma unroll
    for (int mi = 0; mi < 4; mi++)
#pragma unroll
        for (int ni = 0; ni < 4; ni++)
#pragma unroll
            for (int r = 0; r < 4; r++) acc[mi][ni][r] = 0.0f;

    const int KT = K >> 5;   // BK = 32

    auto load_stage = [&](int st, int k0) {
#pragma unroll
        for (int i = 0; i < 2; i++) {
            int c   = t * 2 + i;
            int row = c >> 2;
            int kg  = c & 3;
            cp16(sA(st) + (unsigned)((row * PA + kg * 8) * 2),
                 A + (size_t)(blockRow + row) * K + k0 + kg * 8);
        }
#pragma unroll
        for (int i = 0; i < 2; i++) {
            int c   = t * 2 + i;
            int row = c >> 4;
            int ng  = c & 15;
            cp16(sB(st) + (unsigned)((row * PB + ng * 8) * 2),
                 B + (size_t)(k0 + row) * N + blockCol + ng * 8);
        }
        cp_commit();
    };

    load_stage(0, 0);
    load_stage(1, 32);

    const int l15 = lane & 15;
    const int l16 = lane >> 4;

    for (int kt = 0; kt < KT; kt++) {
        const int cur = kt % 3;
        if (kt + 1 < KT) cp_wait<1>(); else cp_wait<0>();
        __syncthreads();                     // single barrier per iteration
        if (kt + 2 < KT) load_stage((kt + 2) % 3, (kt + 2) * 32);

#pragma unroll
        for (int ks = 0; ks < 2; ks++) {
            unsigned afr[4][4];
#pragma unroll
            for (int mi = 0; mi < 4; mi++) {
                unsigned addr = sA(cur) +
                    (unsigned)(((wm * 64 + mi * 16 + l15) * PA + ks * 16 + l16 * 8) * 2);
                asm volatile("ldmatrix.sync.aligned.m8n8.x4.shared.b16 {%0,%1,%2,%3}, [%4];\n"
                    : "=r"(afr[mi][0]), "=r"(afr[mi][1]), "=r"(afr[mi][2]), "=r"(afr[mi][3])
                    : "r"(addr));
            }
            unsigned bfr[2][4];
#pragma unroll
            for (int n2 = 0; n2 < 2; n2++) {
                unsigned addr = sB(cur) +
                    (unsigned)(((ks * 16 + l15) * PB + wn * 32 + n2 * 16 + l16 * 8) * 2);
                asm volatile("ldmatrix.sync.aligned.m8n8.x4.trans.shared.b16 {%0,%1,%2,%3}, [%4];\n"
                    : "=r"(bfr[n2][0]), "=r"(bfr[n2][1]), "=r"(bfr[n2][2]), "=r"(bfr[n2][3])
                    : "r"(addr));
            }
#pragma unroll
            for (int mi = 0; mi < 4; mi++)
#pragma unroll
                for (int ni = 0; ni < 4; ni++) {
                    unsigned b0 = bfr[ni >> 1][(ni & 1) * 2 + 0];
                    unsigned b1 = bfr[ni >> 1][(ni & 1) * 2 + 1];
                    asm volatile(
                        "mma.sync.aligned.m16n8k16.row.col.f32.bf16.bf16.f32 "
                        "{%0,%1,%2,%3}, {%4,%5,%6,%7}, {%8,%9}, {%0,%1,%2,%3};\n"
                        : "+f"(acc[mi][ni][0]), "+f"(acc[mi][ni][1]),
                          "+f"(acc[mi][ni][2]), "+f"(acc[mi][ni][3])
                        : "r"(afr[mi][0]), "r"(afr[mi][1]), "r"(afr[mi][2]), "r"(afr[mi][3]),
                          "r"(b0), "r"(b1));
                }
        }
    }

    // ---- epilogue ----
    const int grp = lane >> 2;
    const int t4  = lane & 3;
    const float lr = (MODE == 2) ? *scal : 0.0f;

    const float* biasS = bias0;
    bf16* CbS = Cb0;
    int colLocBase;
    int Nout;
    if (MODE == 4) {
        int third = blockIdx.x >> 2;
        biasS = (third == 0) ? bias0 : (third == 1) ? bias1 : bias2;
        CbS   = (third == 0) ? Cb0   : (third == 1) ? Cb1   : Cb2;
        colLocBase = (blockIdx.x & 3) * 128 + wn * 32;
        Nout = MDIM;
    } else {
        colLocBase = blockCol + wn * 32;
        Nout = N;
    }

#pragma unroll
    for (int mi = 0; mi < 4; mi++) {
#pragma unroll
        for (int ni = 0; ni < 4; ni++) {
            int c = colLocBase + ni * 8 + 2 * t4;
            float b0 = 0.f, b1 = 0.f;
            if (MODE == 0 || MODE == 3 || MODE == 4) { b0 = biasS[c]; b1 = biasS[c + 1]; }
#pragma unroll
            for (int h2 = 0; h2 < 2; h2++) {
                size_t r   = (size_t)(blockRow + wm * 64 + mi * 16 + grp + h2 * 8);
                size_t off = r * Nout + c;
                float v0 = acc[mi][ni][h2 * 2 + 0];
                float v1 = acc[mi][ni][h2 * 2 + 1];
                float o0, o1;
                if (MODE == 1)      { o0 = gelu_tanh(v0); o1 = gelu_tanh(v1); }
                else if (MODE == 2) {
                    __nv_bfloat162 e = *reinterpret_cast<const __nv_bfloat162*>(extraB + off);
                    o0 = lr * (__bfloat162float(e.x) - v0);
                    o1 = lr * (__bfloat162float(e.y) - v1);
                }
                else if (MODE == 3) { o0 = v0 + b0 + extraF[off]; o1 = v1 + b1 + extraF[off + 1]; }
                else                { o0 = v0 + b0; o1 = v1 + b1; }
                if (MODE == 3) {
                    *reinterpret_cast<float2*>(Cf + off) = make_float2(o0, o1);
                } else {
                    __nv_bfloat162 p = __floats2bfloat162_rn(o0, o1);
                    *reinterpret_cast<unsigned*>(CbS + off) = *reinterpret_cast<unsigned*>(&p);
                }
            }
        }
    }
}

// ---------------- conversions ------------------------------------------------
__global__ __launch_bounds__(256) void cvt_kernel(const float* __restrict__ s,
                                                  bf16* __restrict__ d, int n4)
{
    int i = blockIdx.x * 256 + threadIdx.x;
    if (i >= n4) return;
    float4 v = reinterpret_cast<const float4*>(s)[i];
    __nv_bfloat162 a = __floats2bfloat162_rn(v.x, v.y);
    __nv_bfloat162 b = __floats2bfloat162_rn(v.z, v.w);
    uint2 ou;
    ou.x = *reinterpret_cast<unsigned*>(&a);
    ou.y = *reinterpret_cast<unsigned*>(&b);
    reinterpret_cast<uint2*>(d)[i] = ou;
}

__global__ __launch_bounds__(256) void cvt_qkv(const float* __restrict__ W,
                                               bf16* __restrict__ dst, int off)
{
    int i = blockIdx.x * 256 + threadIdx.x;
    if (i >= MDIM * MDIM / 4) return;
    float4 v = reinterpret_cast<const float4*>(W)[i];
    int k  = i >> 7;
    int n4 = i & 127;
    __nv_bfloat162 a = __floats2bfloat162_rn(v.x, v.y);
    __nv_bfloat162 b = __floats2bfloat162_rn(v.z, v.w);
    uint2 ou;
    ou.x = *reinterpret_cast<unsigned*>(&a);
    ou.y = *reinterpret_cast<unsigned*>(&b);
    *reinterpret_cast<uint2*>(dst + (size_t)k * 1536 + off + n4 * 4) = ou;
}

// ---------------- LayerNorm in place on bf16, warp per row -------------------
__global__ __launch_bounds__(256) void ln_kernel(bf16* __restrict__ Z,
                                                 const float* __restrict__ g,
                                                 const float* __restrict__ b)
{
    int warp = threadIdx.x >> 5;
    int lane = threadIdx.x & 31;
    size_t row = (size_t)blockIdx.x * 8 + warp;
    bf16* zr = Z + row * MDIM;

    float v[16];
    float s = 0.0f, s2 = 0.0f;
#pragma unroll
    for (int j = 0; j < 2; j++) {
        uint4 u = *reinterpret_cast<const uint4*>(zr + (lane + 32 * j) * 8);
        const unsigned* uu = reinterpret_cast<const unsigned*>(&u);
#pragma unroll
        for (int q2 = 0; q2 < 4; q2++) {
            __nv_bfloat162 p = *reinterpret_cast<const __nv_bfloat162*>(&uu[q2]);
            float a0 = __bfloat162float(p.x), a1 = __bfloat162float(p.y);
            v[j * 8 + q2 * 2 + 0] = a0;
            v[j * 8 + q2 * 2 + 1] = a1;
            s += a0 + a1;
            s2 += a0 * a0 + a1 * a1;
        }
    }
#pragma unroll
    for (int o = 16; o; o >>= 1) {
        s  += __shfl_xor_sync(0xffffffffu, s,  o);
        s2 += __shfl_xor_sync(0xffffffffu, s2, o);
    }
    float mu   = s  * (1.0f / MDIM);
    float var  = s2 * (1.0f / MDIM) - mu * mu;
    float rstd = rsqrtf(var + 1e-5f);
#pragma unroll
    for (int j = 0; j < 2; j++) {
        int cbase = (lane + 32 * j) * 8;
        uint4 pk;
        unsigned* pu = reinterpret_cast<unsigned*>(&pk);
#pragma unroll
        for (int q2 = 0; q2 < 4; q2++) {
            float g0 = g[cbase + q2 * 2], g1 = g[cbase + q2 * 2 + 1];
            float b0 = b[cbase + q2 * 2], b1 = b[cbase + q2 * 2 + 1];
            float o0 = (v[j * 8 + q2 * 2 + 0] - mu) * rstd * g0 + b0;
            float o1 = (v[j * 8 + q2 * 2 + 1] - mu) * rstd * g1 + b1;
            __nv_bfloat162 p = __floats2bfloat162_rn(o0, o1);
            pu[q2] = *reinterpret_cast<unsigned*>(&p);
        }
        *reinterpret_cast<uint4*>(zr + cbase) = pk;
    }
}

// ---------------- 3-phase gated scan -----------------------------------------
__global__ __launch_bounds__(512) void scan1(
    const bf16* __restrict__ u, bf16* __restrict__ loc,
    float* __restrict__ carry, const float* __restrict__ ffp)
{
    int m = threadIdx.x, c = blockIdx.x, b = blockIdx.y;
    float g = 1.0f / (1.0f + expf(-*ffp));
    size_t base = ((size_t)b * SEQ + (size_t)c * CHUNK) * MDIM + m;
    float acc = 0.0f;
    for (int s = 0; s < CHUNK; s++) {
        size_t idx = base + (size_t)s * MDIM;
        acc = fmaf(g, acc, __bfloat162float(u[idx]));
        loc[idx] = __float2bfloat16(acc);
    }
    carry[((size_t)b * NCHUNK + c) * MDIM + m] = acc;
}

__global__ __launch_bounds__(512) void scan2(
    const float* __restrict__ carry, float* __restrict__ pref,
    const float* __restrict__ ffp)
{
    int m = threadIdx.x, b = blockIdx.x;
    float g  = 1.0f / (1.0f + expf(-*ffp));
    float gL = powf(g, (float)CHUNK);
    float P = 0.0f;
    for (int c = 0; c < NCHUNK; c++) {
        size_t idx = ((size_t)b * NCHUNK + c) * MDIM + m;
        pref[idx] = P;
        P = fmaf(gL, P, carry[idx]);
    }
}

__global__ __launch_bounds__(512) void scan3(
    const bf16* __restrict__ loc, const float* __restrict__ pref,
    const bf16* __restrict__ q, bf16* __restrict__ ret,
    const float* __restrict__ ffp)
{
    int m = threadIdx.x, c = blockIdx.x, b = blockIdx.y;
    float g = 1.0f / (1.0f + expf(-*ffp));
    float P = pref[((size_t)b * NCHUNK + c) * MDIM + m];
    size_t base = ((size_t)b * SEQ + (size_t)c * CHUNK) * MDIM + m;
    float wgt = g;
    for (int s = 0; s < CHUNK; s++) {
        size_t idx = base + (size_t)s * MDIM;
        float mem = fmaf(wgt, P, __bfloat162float(loc[idx]));
        ret[idx] = __float2bfloat16(__bfloat162float(q[idx]) * mem);
        wgt *= g;
    }
}

// ---------------- launch ------------------------------------------------------
extern "C" void kernel_launch(void* const* d_in, const int* in_sizes, int n_in,
                              void* d_out, int out_size)
{
    const float* x    = (const float*)d_in[0];
    const float* Wd   = (const float*)d_in[1];
    const float* bd   = (const float*)d_in[2];
    const float* Wq   = (const float*)d_in[3];
    const float* bq   = (const float*)d_in[4];
    const float* Wk   = (const float*)d_in[5];
    const float* bk   = (const float*)d_in[6];
    const float* Wv   = (const float*)d_in[7];
    const float* bv   = (const float*)d_in[8];
    const float* gq   = (const float*)d_in[9];
    const float* bqln = (const float*)d_in[10];
    const float* gk   = (const float*)d_in[11];
    const float* bkln = (const float*)d_in[12];
    const float* W1   = (const float*)d_in[13];
    const float* W2   = (const float*)d_in[14];
    const float* Wu   = (const float*)d_in[15];
    const float* bu   = (const float*)d_in[16];
    const float* lr   = (const float*)d_in[17];
    const float* ff   = (const float*)d_in[18];
    float* out = (float*)d_out;

    bf16 *xb, *hb, *qh, *kh, *vb, *pb, *ub, *lc, *rb;
    bf16 *Wdb, *Wqkv, *W1b, *W2b, *Wub;
    float *carry, *pref;
    cudaGetSymbolAddress((void**)&xb, g_xb);
    cudaGetSymbolAddress((void**)&hb, g_hb);
    cudaGetSymbolAddress((void**)&qh, g_qh);
    cudaGetSymbolAddress((void**)&kh, g_kh);
    cudaGetSymbolAddress((void**)&vb, g_vb);
    cudaGetSymbolAddress((void**)&pb, g_pb);
    cudaGetSymbolAddress((void**)&ub, g_ub);
    cudaGetSymbolAddress((void**)&lc, g_lc);
    cudaGetSymbolAddress((void**)&rb, g_rb);
    cudaGetSymbolAddress((void**)&carry, g_carry);
    cudaGetSymbolAddress((void**)&pref,  g_pref);
    cudaGetSymbolAddress((void**)&Wdb,  g_Wdb);
    cudaGetSymbolAddress((void**)&Wqkv, g_Wqkv);
    cudaGetSymbolAddress((void**)&W1b,  g_W1b);
    cudaGetSymbolAddress((void**)&W2b,  g_W2b);
    cudaGetSymbolAddress((void**)&Wub,  g_Wub);

    cudaFuncSetAttribute(mma_gemm<0>, cudaFuncAttributeMaxDynamicSharedMemorySize, SMEM_TOT);
    cudaFuncSetAttribute(mma_gemm<1>, cudaFuncAttributeMaxDynamicSharedMemorySize, SMEM_TOT);
    cudaFuncSetAttribute(mma_gemm<2>, cudaFuncAttributeMaxDynamicSharedMemorySize, SMEM_TOT);
    cudaFuncSetAttribute(mma_gemm<3>, cudaFuncAttributeMaxDynamicSharedMemorySize, SMEM_TOT);
    cudaFuncSetAttribute(mma_gemm<4>, cudaFuncAttributeMaxDynamicSharedMemorySize, SMEM_TOT);

    dim3 tb(256);
    dim3 gM(MDIM / 128, ROWS / 128);       // (4, 256)
    dim3 gQKV(3 * MDIM / 128, ROWS / 128); // (12, 256)
    dim3 gD(DDIM / 128, ROWS / 128);       // (8, 256)

    // 1-4: converts needed by the h-GEMM (+ W1/W2 to fill slots)
    cvt_kernel<<<ROWS * DDIM / 4 / 256, 256>>>(x, xb, ROWS * DDIM / 4);
    cvt_kernel<<<DDIM * MDIM / 4 / 256, 256>>>(Wd, Wdb, DDIM * MDIM / 4);
    cvt_kernel<<<MDIM * MDIM / 4 / 256, 256>>>(W1, W1b, MDIM * MDIM / 4);
    cvt_kernel<<<MDIM * MDIM / 4 / 256, 256>>>(W2, W2b, MDIM * MDIM / 4);
    // 5: h = x@Wd + bd   <-- ncu capture target (5th launch)
    mma_gemm<0><<<gM, tb, SMEM_TOT>>>(xb, Wdb, bd, nullptr, nullptr, nullptr, nullptr,
                                      nullptr, nullptr, hb, nullptr, nullptr, DDIM, MDIM);
    // 6-8: qkv weight converts
    cvt_qkv<<<MDIM * MDIM / 4 / 256, 256>>>(Wq, Wqkv, 0);
    cvt_qkv<<<MDIM * MDIM / 4 / 256, 256>>>(Wk, Wqkv, 512);
    cvt_qkv<<<MDIM * MDIM / 4 / 256, 256>>>(Wv, Wqkv, 1024);
    // 9: fused qkv
    mma_gemm<4><<<gQKV, tb, SMEM_TOT>>>(hb, Wqkv, bq, bk, bv, nullptr, nullptr,
                                        nullptr, nullptr, qh, kh, vb, MDIM, 3 * MDIM);
    // 10: Wu convert
    cvt_kernel<<<MDIM * DDIM / 4 / 256, 256>>>(Wu, Wub, MDIM * DDIM / 4);
    // 11-12: LayerNorms
    ln_kernel<<<ROWS / 8, 256>>>(qh, gq, bqln);
    ln_kernel<<<ROWS / 8, 256>>>(kh, gk, bkln);
    // 13: P = gelu(k@W1)
    mma_gemm<1><<<gM, tb, SMEM_TOT>>>(kh, W1b, nullptr, nullptr, nullptr, nullptr, nullptr,
                                      nullptr, nullptr, pb, nullptr, nullptr, MDIM, MDIM);
    // 14: u = lr*(v - P@W2)
    mma_gemm<2><<<gM, tb, SMEM_TOT>>>(pb, W2b, nullptr, nullptr, nullptr, nullptr, vb,
                                      lr, nullptr, ub, nullptr, nullptr, MDIM, MDIM);
    // 15-17: scan
    scan1<<<dim3(NCHUNK, BATCH), MDIM>>>(ub, lc, carry, ff);
    scan2<<<BATCH, MDIM>>>(carry, pref, ff);
    scan3<<<dim3(NCHUNK, BATCH), MDIM>>>(lc, pref, qh, rb, ff);
    // 18: out = x + ret@Wu + bu
    mma_gemm<3><<<gD, tb, SMEM_TOT>>>(rb, Wub, bu, nullptr, nullptr, x, nullptr,
                                      nullptr, out, nullptr, nullptr, nullptr, MDIM, DDIM);
}